// round 10
// baseline (speedup 1.0000x reference)
#include <cuda_runtime.h>
#include <cuda_fp16.h>
#include <mma.h>
#include <cstdint>

using namespace nvcuda;

#define BATCH 4
#define CH    512
#define CQK   64
#define NPIX  4096
#define EPS   1e-5f

#define BM 128
#define BN 128
#define BK 32
#define NSTG 3
#define NTHR 128
#define LDA0 40    // As[m][k] rows of BK+8 half  (AMODE 0: k-contig gmem)
#define LDA1 136   // As[k][m] rows of BM+8 half  (AMODE 1: m-contig gmem)
#define LDB0 136   // Bs[k][n] rows of BN+8 half  (BMODE 0: n-contig gmem)
#define LDB1 40    // Bs[n][k] rows of BK+8 half  (BMODE 1: k-contig gmem)

// ---------------- scratch (device globals; allocation-free) ----------------
__device__ __half g_xh[(size_t)BATCH * CH * NPIX];
__device__ __half g_wqh[CQK * CH];
__device__ __half g_wkh[CQK * CH];
__device__ __half g_wvh[CH * CH];
__device__ __half g_qh[(size_t)BATCH * CQK * NPIX];
__device__ __half g_kh[(size_t)BATCH * CQK * NPIX];
__device__ __half g_vh[(size_t)BATCH * CH * NPIX];
__device__ float  g_ef[(size_t)BATCH * NPIX * NPIX];     // energy, fp32 (direct store)
__device__ __half g_attnh[(size_t)BATCH * NPIX * NPIX];
__device__ float  g_ao[(size_t)BATCH * CH * NPIX];
__device__ float  g_mean[CH];
__device__ float  g_var[CH];

// ---------------- cp.async helpers ----------------
__device__ __forceinline__ void cp16(__half* dst, const __half* src) {
    unsigned d = (unsigned)__cvta_generic_to_shared(dst);
    asm volatile("cp.async.cg.shared.global [%0], [%1], 16;\n" :: "r"(d), "l"(src));
}
__device__ __forceinline__ void cp_commit() {
    asm volatile("cp.async.commit_group;\n" ::: "memory");
}
__device__ __forceinline__ void cp_wait1() {
    asm volatile("cp.async.wait_group 1;\n" ::: "memory");
}
__device__ __forceinline__ void cp_wait0() {
    asm volatile("cp.async.wait_group 0;\n" ::: "memory");
}

// ---------------- fp16 WMMA GEMM: 64x64 warp tiles, 3-stage cp.async ----------------
// D[b](m,n) = sum_k A(m,k) * B(k,n) (+ bias[m])
// AMODE 0: A(m,k) at A[m*lda + k]  (k contig) | AMODE 1: A(m,k) at A[k*lda + m] (m contig)
// BMODE 0: B(k,n) at B[k*ldb + n]  (n contig) | BMODE 1: B(k,n) at B[n*ldb + k] (k contig)
// DUAL: A rows 0..63 from A0, 64..127 from A1 (weights; Abatch ignored).
// OUTH: D is half (D0/D1 split at row 64 when DUAL), else fp32 D0 (direct, no staging).
template<int AMODE, int BMODE, bool DUAL, bool BIAS, bool OUTH>
__global__ __launch_bounds__(NTHR, 2) void hgemm(
    const __half* __restrict__ A0, const __half* __restrict__ A1,
    size_t Abatch, int lda,
    const __half* __restrict__ B, size_t Bbatch, int ldb,
    void* __restrict__ D0, void* __restrict__ D1, size_t Dbatch, int ldd,
    const float* __restrict__ bias0, const float* __restrict__ bias1, int K)
{
    constexpr int ASZ = (AMODE == 0) ? BM * LDA0 : BK * LDA1;
    constexpr int BSZ = (BMODE == 0) ? BK * LDB0 : BN * LDB1;
    constexpr int STG = ASZ + BSZ;
    extern __shared__ __half sm[];

    const int bz = blockIdx.z;
    const __half* Ab = A0 + (size_t)bz * Abatch;
    const __half* Bb = B + (size_t)bz * Bbatch;

    const int m0 = blockIdx.y * BM;
    const int n0 = blockIdx.x * BN;
    const int tid = threadIdx.x;
    const int warp = tid >> 5;
    const int lane = tid & 31;
    const int wm = (warp >> 1) * 64;   // warp tile 64(m) x 64(n)
    const int wn = (warp & 1) * 64;

    wmma::fragment<wmma::accumulator, 16, 16, 16, float> acc[4][4];
#pragma unroll
    for (int i = 0; i < 4; i++)
#pragma unroll
        for (int j = 0; j < 4; j++)
            wmma::fill_fragment(acc[i][j], 0.0f);

    auto load_tile = [&](int s, int k0) {
        __half* As = sm + s * STG;
        __half* Bs = As + ASZ;
#pragma unroll
        for (int r = 0; r < 4; r++) {
            int c = tid + r * NTHR;
            if (AMODE == 0) {
                int m = c >> 2, jc = c & 3;
                const __half* src;
                if (DUAL)
                    src = (m < 64 ? Ab + (size_t)m * lda
                                  : A1 + (size_t)(m - 64) * lda) + k0 + jc * 8;
                else
                    src = Ab + (size_t)(m0 + m) * lda + k0 + jc * 8;
                cp16(&As[m * LDA0 + jc * 8], src);
            } else {
                int k = c >> 4, mc = c & 15;
                cp16(&As[k * LDA1 + mc * 8],
                     Ab + (size_t)(k0 + k) * lda + m0 + mc * 8);
            }
        }
#pragma unroll
        for (int r = 0; r < 4; r++) {
            int c = tid + r * NTHR;
            if (BMODE == 0) {
                int k = c >> 4, nc = c & 15;
                cp16(&Bs[k * LDB0 + nc * 8],
                     Bb + (size_t)(k0 + k) * ldb + n0 + nc * 8);
            } else {
                int n = c >> 2, kc = c & 3;
                cp16(&Bs[n * LDB1 + kc * 8],
                     Bb + (size_t)(n0 + n) * ldb + k0 + kc * 8);
            }
        }
    };

    auto compute_tile = [&](int s) {
        const __half* As = sm + s * STG;
        const __half* Bs = As + ASZ;
#pragma unroll
        for (int ks = 0; ks < BK; ks += 16) {
            wmma::fragment<wmma::matrix_a, 16, 16, 16, __half, wmma::row_major> ar[4];
            wmma::fragment<wmma::matrix_a, 16, 16, 16, __half, wmma::col_major> ac[4];
#pragma unroll
            for (int i = 0; i < 4; i++) {
                if (AMODE == 0)
                    wmma::load_matrix_sync(ar[i], &As[(wm + i * 16) * LDA0 + ks], LDA0);
                else
                    wmma::load_matrix_sync(ac[i], &As[ks * LDA1 + wm + i * 16], LDA1);
            }
#pragma unroll
            for (int j = 0; j < 4; j++) {
                wmma::fragment<wmma::matrix_b, 16, 16, 16, __half, wmma::row_major> br;
                wmma::fragment<wmma::matrix_b, 16, 16, 16, __half, wmma::col_major> bc;
                if (BMODE == 0)
                    wmma::load_matrix_sync(br, &Bs[ks * LDB0 + wn + j * 16], LDB0);
                else
                    wmma::load_matrix_sync(bc, &Bs[(wn + j * 16) * LDB1 + ks], LDB1);
#pragma unroll
                for (int i = 0; i < 4; i++) {
                    if (AMODE == 0 && BMODE == 0) wmma::mma_sync(acc[i][j], ar[i], br, acc[i][j]);
                    if (AMODE == 0 && BMODE == 1) wmma::mma_sync(acc[i][j], ar[i], bc, acc[i][j]);
                    if (AMODE == 1 && BMODE == 0) wmma::mma_sync(acc[i][j], ac[i], br, acc[i][j]);
                    if (AMODE == 1 && BMODE == 1) wmma::mma_sync(acc[i][j], ac[i], bc, acc[i][j]);
                }
            }
        }
    };

    const int KT = K / BK;
    load_tile(0, 0);
    cp_commit();
    if (KT > 1) { load_tile(1, BK); cp_commit(); }

    for (int kt = 0; kt < KT; kt++) {
        if (kt + 1 < KT) cp_wait1(); else cp_wait0();
        __syncthreads();
        if (kt + 2 < KT) {
            load_tile((kt + 2) % NSTG, (kt + 2) * BK);
            cp_commit();
        }
        compute_tile(kt % NSTG);
    }

    // ---- epilogue ----
    if (!OUTH) {
        // direct fp32 store, no smem staging
        float* Db = (float*)D0 + (size_t)bz * Dbatch;
#pragma unroll
        for (int i = 0; i < 4; i++) {
            int gm = m0 + wm + i * 16;
#pragma unroll
            for (int j = 0; j < 4; j++)
                wmma::store_matrix_sync(Db + (size_t)gm * ldd + n0 + wn + j * 16,
                                        acc[i][j], ldd, wmma::mem_row_major);
        }
    } else {
        __syncthreads();                    // done reading pipeline smem
        float* stg = (float*)sm + warp * 256;
        const int sr = lane >> 1;           // 0..15 row within 16x16 frag
        const int sc = (lane & 1) * 8;      // 0 or 8: col group
#pragma unroll
        for (int i = 0; i < 4; i++) {
            int gm = m0 + wm + i * 16 + sr;
            float bb = 0.0f;
            __half* outp;
            int row;
            if (DUAL) {
                if (BIAS) bb = (gm < 64) ? bias0[gm] : bias1[gm - 64];
                outp = (__half*)(gm < 64 ? D0 : D1) + (size_t)bz * Dbatch;
                row = gm & 63;
            } else {
                if (BIAS) bb = bias0[gm];
                outp = (__half*)D0 + (size_t)bz * Dbatch;
                row = gm;
            }
#pragma unroll
            for (int j = 0; j < 4; j++) {
                wmma::store_matrix_sync(stg, acc[i][j], 16, wmma::mem_row_major);
                __syncwarp();
                const float* src = stg + sr * 16 + sc;
                __half2 h[4];
#pragma unroll
                for (int p = 0; p < 4; p++)
                    h[p] = __floats2half2_rn(src[2 * p] + bb, src[2 * p + 1] + bb);
                int gn = n0 + wn + j * 16 + sc;
                *(uint4*)(outp + (size_t)row * ldd + gn) = *(uint4*)h;
                __syncwarp();
            }
        }
    }
}

// ---------------- fused f32 -> f16 conversion (x, Wq, Wk, Wv in one launch) ----------------
#define NX4 (BATCH * CH * NPIX / 4)   // 2097152
#define NQ4 (CQK * CH / 4)            // 8192
#define NV4 (CH * CH / 4)             // 65536
__global__ __launch_bounds__(256) void f2h_all(
    const float* __restrict__ x,  const float* __restrict__ wq,
    const float* __restrict__ wk, const float* __restrict__ wv,
    __half* __restrict__ xh, __half* __restrict__ wqh,
    __half* __restrict__ wkh, __half* __restrict__ wvh)
{
    int i = blockIdx.x * 256 + threadIdx.x;
    const float* src; __half* dst; int off;
    if (i < NX4)                       { src = x;  dst = xh;  off = i; }
    else if (i < NX4 + NQ4)            { src = wq; dst = wqh; off = i - NX4; }
    else if (i < NX4 + 2 * NQ4)        { src = wk; dst = wkh; off = i - NX4 - NQ4; }
    else if (i < NX4 + 2 * NQ4 + NV4)  { src = wv; dst = wvh; off = i - NX4 - 2 * NQ4; }
    else return;
    float4 v = ((const float4*)src)[off];
    __half2* o = (__half2*)dst + 2 * (size_t)off;
    o[0] = __floats2half2_rn(v.x, v.y);
    o[1] = __floats2half2_rn(v.z, v.w);
}

// ---------------- row softmax: fp32 energy in, no max pass, fp16 attn out ----------------
__global__ __launch_bounds__(256) void softmax_rows(const float* __restrict__ E,
                                                    __half* __restrict__ A)
{
    __shared__ float row[NPIX];
    __shared__ float wsum[8];
    const float4* e4 = (const float4*)(E + (size_t)blockIdx.x * NPIX);
    __half2* a2 = (__half2*)(A + (size_t)blockIdx.x * NPIX);
    float4* row4 = (float4*)row;
    const int tid = threadIdx.x;
    const int lane = tid & 31, warp = tid >> 5;

    float sum = 0.0f;
#pragma unroll
    for (int i = 0; i < 4; i++) {
        int j = tid + i * 256;                 // 1024 float4 per row
        float4 v = e4[j];
        v.x = __expf(v.x); v.y = __expf(v.y);
        v.z = __expf(v.z); v.w = __expf(v.w);
        row4[j] = v;
        sum += v.x + v.y + v.z + v.w;
    }
#pragma unroll
    for (int o = 16; o > 0; o >>= 1)
        sum += __shfl_xor_sync(0xFFFFFFFFu, sum, o);
    if (lane == 0) wsum[warp] = sum;
    __syncthreads();
    float tot = 0.0f;
#pragma unroll
    for (int w = 0; w < 8; w++) tot += wsum[w];
    const float inv = 1.0f / tot;

#pragma unroll
    for (int i = 0; i < 4; i++) {
        int j = tid + i * 256;
        float4 v = row4[j];
        a2[2 * j]     = __floats2half2_rn(v.x * inv, v.y * inv);
        a2[2 * j + 1] = __floats2half2_rn(v.z * inv, v.w * inv);
    }
}

// ---------------- residual write + per-channel batch stats (fused) ----------------
__global__ __launch_bounds__(256) void residual_stats(
    const float* __restrict__ ao, const float* __restrict__ x,
    const float* __restrict__ gamma, float* __restrict__ out,
    float* __restrict__ mean, float* __restrict__ var)
{
    __shared__ float w1[8], w2[8];
    const int c = blockIdx.x;
    const float g = gamma[0];
    const int lane = threadIdx.x & 31, warp = threadIdx.x >> 5;
    float s1 = 0.0f, s2 = 0.0f;
#pragma unroll
    for (int b = 0; b < BATCH; b++) {
        const size_t base4 = ((size_t)b * CH + c) * (NPIX / 4);
        const float4* a4 = (const float4*)ao + base4;
        const float4* x4 = (const float4*)x + base4;
        float4* o4 = (float4*)out + base4;
        for (int n = threadIdx.x; n < NPIX / 4; n += 256) {
            float4 av = a4[n], xv = x4[n];
            float4 r;
            r.x = g * av.x + xv.x; r.y = g * av.y + xv.y;
            r.z = g * av.z + xv.z; r.w = g * av.w + xv.w;
            o4[n] = r;
            s1 += r.x + r.y + r.z + r.w;
            s2 += r.x * r.x + r.y * r.y + r.z * r.z + r.w * r.w;
        }
    }
#pragma unroll
    for (int o = 16; o > 0; o >>= 1) {
        s1 += __shfl_xor_sync(0xFFFFFFFFu, s1, o);
        s2 += __shfl_xor_sync(0xFFFFFFFFu, s2, o);
    }
    if (lane == 0) { w1[warp] = s1; w2[warp] = s2; }
    __syncthreads();
    if (threadIdx.x == 0) {
        float t1 = 0.0f, t2 = 0.0f;
#pragma unroll
        for (int w = 0; w < 8; w++) { t1 += w1[w]; t2 += w2[w]; }
        const float cnt = (float)(BATCH * NPIX);
        float m = t1 / cnt;
        mean[c] = m;
        var[c] = t2 / cnt - m * m;
    }
}

// ---------------- BN apply, in place on d_out ----------------
__global__ __launch_bounds__(256) void bn_apply(
    float* __restrict__ out, const float* __restrict__ mean,
    const float* __restrict__ var, const float* __restrict__ w,
    const float* __restrict__ bb)
{
    size_t i4 = (size_t)blockIdx.x * 256 + threadIdx.x;
    int c = (int)((i4 >> 10) & (CH - 1));
    float sc = rsqrtf(var[c] + EPS) * w[c];
    float sh = bb[c] - mean[c] * sc;
    float4 r = ((float4*)out)[i4];
    r.x = r.x * sc + sh;
    r.y = r.y * sc + sh;
    r.z = r.z * sc + sh;
    r.w = r.w * sc + sh;
    ((float4*)out)[i4] = r;
}

// ---------------- launch ----------------
extern "C" void kernel_launch(void* const* d_in, const int* in_sizes, int n_in,
                              void* d_out, int out_size)
{
    const float* x     = (const float*)d_in[0];
    const float* Wq    = (const float*)d_in[1];
    const float* bq    = (const float*)d_in[2];
    const float* Wk    = (const float*)d_in[3];
    const float* bk    = (const float*)d_in[4];
    const float* Wv    = (const float*)d_in[5];
    const float* bv    = (const float*)d_in[6];
    const float* gamma = (const float*)d_in[7];
    const float* bn_w  = (const float*)d_in[8];
    const float* bn_b  = (const float*)d_in[9];
    float* out = (float*)d_out;

    __half *xh, *wqh, *wkh, *wvh, *qh, *kh, *vh, *attnh;
    float *ef, *ao, *mean, *var;
    cudaGetSymbolAddress((void**)&xh,     g_xh);
    cudaGetSymbolAddress((void**)&wqh,    g_wqh);
    cudaGetSymbolAddress((void**)&wkh,    g_wkh);
    cudaGetSymbolAddress((void**)&wvh,    g_wvh);
    cudaGetSymbolAddress((void**)&qh,     g_qh);
    cudaGetSymbolAddress((void**)&kh,     g_kh);
    cudaGetSymbolAddress((void**)&vh,     g_vh);
    cudaGetSymbolAddress((void**)&ef,     g_ef);
    cudaGetSymbolAddress((void**)&attnh,  g_attnh);
    cudaGetSymbolAddress((void**)&ao,     g_ao);
    cudaGetSymbolAddress((void**)&mean,   g_mean);
    cudaGetSymbolAddress((void**)&var,    g_var);

    // dynamic smem sizes (3 stages)
    const int smem00 = NSTG * (BM * LDA0 + BK * LDB0) * (int)sizeof(__half); // 56832
    const int smem10 = NSTG * (BK * LDA1 + BK * LDB0) * (int)sizeof(__half); // 52224
    const int smem01 = NSTG * (BM * LDA0 + BN * LDB1) * (int)sizeof(__half); // 61440
    cudaFuncSetAttribute(hgemm<0, 0, true,  true,  true>,
                         cudaFuncAttributeMaxDynamicSharedMemorySize, smem00);
    cudaFuncSetAttribute(hgemm<0, 0, false, true,  true>,
                         cudaFuncAttributeMaxDynamicSharedMemorySize, smem00);
    cudaFuncSetAttribute(hgemm<1, 0, false, false, false>,
                         cudaFuncAttributeMaxDynamicSharedMemorySize, smem10);
    cudaFuncSetAttribute(hgemm<0, 1, false, false, false>,
                         cudaFuncAttributeMaxDynamicSharedMemorySize, smem01);

    const size_t xbs = (size_t)CH * NPIX;     // x / xh / vh / ao batch stride
    const size_t qbs = (size_t)CQK * NPIX;    // qh / kh batch stride
    const size_t ebs = (size_t)NPIX * NPIX;   // energy / attn batch stride

    // 1) convert inputs to half (single launch)
    f2h_all<<<(NX4 + 2 * NQ4 + NV4 + 255) / 256, 256>>>(
        x, Wq, Wk, Wv, xh, wqh, wkh, wvh);

    // 2) q,k = (Wq||Wk) @ x  -> half. M=128 (dual 64+64), K=512
    hgemm<0, 0, true, true, true><<<dim3(NPIX / BN, 1, BATCH), NTHR, smem00>>>(
        wqh, wkh, 0, CH, xh, xbs, NPIX, qh, kh, qbs, NPIX, bq, bk, CH);

    // 3) v = Wv @ x -> half. M=512, K=512
    hgemm<0, 0, false, true, true><<<dim3(NPIX / BN, CH / BM, BATCH), NTHR, smem00>>>(
        wvh, nullptr, 0, CH, xh, xbs, NPIX, vh, nullptr, xbs, NPIX, bv, nullptr, CH);

    // 4) energy(i,j) = sum_k q(k,i)*k(k,j) -> fp32 direct store. M=N=4096, K=64
    hgemm<1, 0, false, false, false><<<dim3(NPIX / BN, NPIX / BM, BATCH), NTHR, smem10>>>(
        qh, nullptr, qbs, NPIX, kh, qbs, NPIX, ef, nullptr, ebs, NPIX,
        nullptr, nullptr, CQK);

    // 5) softmax rows (fp32 in, no max pass) -> half attn
    softmax_rows<<<BATCH * NPIX, 256>>>(ef, attnh);

    // 6) ao(c,i) = sum_j v(c,j)*attn(i,j) -> fp32. M=512, K=4096
    hgemm<0, 1, false, false, false><<<dim3(NPIX / BN, CH / BM, BATCH), NTHR, smem01>>>(
        vh, nullptr, xbs, NPIX, attnh, ebs, NPIX, ao, nullptr, xbs, NPIX,
        nullptr, nullptr, NPIX);

    // 7) residual write + stats (fused), then BN in place on d_out
    residual_stats<<<CH, 256>>>(ao, x, gamma, out, mean, var);
    bn_apply<<<(unsigned)(((size_t)BATCH * CH * NPIX / 4) / 256), 256>>>(
        out, mean, var, bn_w, bn_b);
}

// round 14
// speedup vs baseline: 1.0308x; 1.0308x over previous
#include <cuda_runtime.h>
#include <cuda_fp16.h>
#include <mma.h>
#include <cstdint>

using namespace nvcuda;

#define BATCH 4
#define CH    512
#define CQK   64
#define NPIX  4096
#define EPS   1e-5f

#define BM 128
#define BN 128
#define BK 32
#define NSTG 3
#define NTHR 256
#define LDA0 40    // As[m][k] rows of BK+8 half  (AMODE 0: k-contig gmem)
#define LDA1 136   // As[k][m] rows of BM+8 half  (AMODE 1: m-contig gmem)
#define LDB0 136   // Bs[k][n] rows of BN+8 half  (BMODE 0: n-contig gmem)
#define LDB1 40    // Bs[n][k] rows of BK+8 half  (BMODE 1: k-contig gmem)

// ---------------- scratch (device globals; allocation-free) ----------------
__device__ __half g_xh[(size_t)BATCH * CH * NPIX];
__device__ __half g_wqh[CQK * CH];
__device__ __half g_wkh[CQK * CH];
__device__ __half g_wvh[CH * CH];
__device__ __half g_qh[(size_t)BATCH * CQK * NPIX];
__device__ __half g_kh[(size_t)BATCH * CQK * NPIX];
__device__ __half g_vh[(size_t)BATCH * CH * NPIX];
__device__ __half g_eh[(size_t)BATCH * NPIX * NPIX];     // energy, fp16
__device__ __half g_attnh[(size_t)BATCH * NPIX * NPIX];
__device__ __half g_aoh[(size_t)BATCH * CH * NPIX];      // attention out, fp16
__device__ float  g_mean[CH];
__device__ float  g_var[CH];

// ---------------- cp.async helpers ----------------
__device__ __forceinline__ void cp16(__half* dst, const __half* src) {
    unsigned d = (unsigned)__cvta_generic_to_shared(dst);
    asm volatile("cp.async.cg.shared.global [%0], [%1], 16;\n" :: "r"(d), "l"(src));
}
__device__ __forceinline__ void cp_commit() {
    asm volatile("cp.async.commit_group;\n" ::: "memory");
}
__device__ __forceinline__ void cp_wait1() {
    asm volatile("cp.async.wait_group 1;\n" ::: "memory");
}
__device__ __forceinline__ void cp_wait0() {
    asm volatile("cp.async.wait_group 0;\n" ::: "memory");
}

// ---------------- fp16 WMMA GEMM: 8 warps, 32x64 warp tiles, 3-stage cp.async ----------------
// D[b](m,n) = sum_k A(m,k) * B(k,n) (+ bias[m])
// AMODE 0: A(m,k) at A[m*lda + k]  (k contig) | AMODE 1: A(m,k) at A[k*lda + m] (m contig)
// BMODE 0: B(k,n) at B[k*ldb + n]  (n contig) | BMODE 1: B(k,n) at B[n*ldb + k] (k contig)
// DUAL: A rows 0..63 from A0, 64..127 from A1 (weights; Abatch ignored).
// OUTH: D is half (D0/D1 split at row 64 when DUAL), else fp32 D0 direct.
template<int AMODE, int BMODE, bool DUAL, bool BIAS, bool OUTH>
__global__ __launch_bounds__(NTHR, 2) void hgemm(
    const __half* __restrict__ A0, const __half* __restrict__ A1,
    size_t Abatch, int lda,
    const __half* __restrict__ B, size_t Bbatch, int ldb,
    void* __restrict__ D0, void* __restrict__ D1, size_t Dbatch, int ldd,
    const float* __restrict__ bias0, const float* __restrict__ bias1, int K)
{
    constexpr int ASZ = (AMODE == 0) ? BM * LDA0 : BK * LDA1;
    constexpr int BSZ = (BMODE == 0) ? BK * LDB0 : BN * LDB1;
    constexpr int STG = ASZ + BSZ;
    extern __shared__ __half sm[];

    const int bz = blockIdx.z;
    const __half* Ab = A0 + (size_t)bz * Abatch;
    const __half* Bb = B + (size_t)bz * Bbatch;

    const int m0 = blockIdx.y * BM;
    const int n0 = blockIdx.x * BN;
    const int tid = threadIdx.x;
    const int warp = tid >> 5;
    const int lane = tid & 31;
    const int wm = (warp >> 1) * 32;   // warp tile 32(m) x 64(n)
    const int wn = (warp & 1) * 64;

    wmma::fragment<wmma::accumulator, 16, 16, 16, float> acc[2][4];
#pragma unroll
    for (int i = 0; i < 2; i++)
#pragma unroll
        for (int j = 0; j < 4; j++)
            wmma::fill_fragment(acc[i][j], 0.0f);

    auto load_tile = [&](int s, int k0) {
        __half* As = sm + s * STG;
        __half* Bs = As + ASZ;
#pragma unroll
        for (int r = 0; r < 2; r++) {
            int c = tid + r * NTHR;
            if (AMODE == 0) {
                int m = c >> 2, jc = c & 3;
                const __half* src;
                if (DUAL)
                    src = (m < 64 ? Ab + (size_t)m * lda
                                  : A1 + (size_t)(m - 64) * lda) + k0 + jc * 8;
                else
                    src = Ab + (size_t)(m0 + m) * lda + k0 + jc * 8;
                cp16(&As[m * LDA0 + jc * 8], src);
            } else {
                int k = c >> 4, mc = c & 15;
                cp16(&As[k * LDA1 + mc * 8],
                     Ab + (size_t)(k0 + k) * lda + m0 + mc * 8);
            }
        }
#pragma unroll
        for (int r = 0; r < 2; r++) {
            int c = tid + r * NTHR;
            if (BMODE == 0) {
                int k = c >> 4, nc = c & 15;
                cp16(&Bs[k * LDB0 + nc * 8],
                     Bb + (size_t)(k0 + k) * ldb + n0 + nc * 8);
            } else {
                int n = c >> 2, kc = c & 3;
                cp16(&Bs[n * LDB1 + kc * 8],
                     Bb + (size_t)(n0 + n) * ldb + k0 + kc * 8);
            }
        }
    };

    auto compute_tile = [&](int s) {
        const __half* As = sm + s * STG;
        const __half* Bs = As + ASZ;
#pragma unroll
        for (int ks = 0; ks < BK; ks += 16) {
            wmma::fragment<wmma::matrix_a, 16, 16, 16, __half, wmma::row_major> ar[2];
            wmma::fragment<wmma::matrix_a, 16, 16, 16, __half, wmma::col_major> ac[2];
#pragma unroll
            for (int i = 0; i < 2; i++) {
                if (AMODE == 0)
                    wmma::load_matrix_sync(ar[i], &As[(wm + i * 16) * LDA0 + ks], LDA0);
                else
                    wmma::load_matrix_sync(ac[i], &As[ks * LDA1 + wm + i * 16], LDA1);
            }
#pragma unroll
            for (int j = 0; j < 4; j++) {
                wmma::fragment<wmma::matrix_b, 16, 16, 16, __half, wmma::row_major> br;
                wmma::fragment<wmma::matrix_b, 16, 16, 16, __half, wmma::col_major> bc;
                if (BMODE == 0)
                    wmma::load_matrix_sync(br, &Bs[ks * LDB0 + wn + j * 16], LDB0);
                else
                    wmma::load_matrix_sync(bc, &Bs[(wn + j * 16) * LDB1 + ks], LDB1);
#pragma unroll
                for (int i = 0; i < 2; i++) {
                    if (AMODE == 0 && BMODE == 0) wmma::mma_sync(acc[i][j], ar[i], br, acc[i][j]);
                    if (AMODE == 0 && BMODE == 1) wmma::mma_sync(acc[i][j], ar[i], bc, acc[i][j]);
                    if (AMODE == 1 && BMODE == 0) wmma::mma_sync(acc[i][j], ac[i], br, acc[i][j]);
                    if (AMODE == 1 && BMODE == 1) wmma::mma_sync(acc[i][j], ac[i], bc, acc[i][j]);
                }
            }
        }
    };

    const int KT = K / BK;
    load_tile(0, 0);
    cp_commit();
    if (KT > 1) { load_tile(1, BK); cp_commit(); }

    for (int kt = 0; kt < KT; kt++) {
        if (kt + 1 < KT) cp_wait1(); else cp_wait0();
        __syncthreads();
        if (kt + 2 < KT) {
            load_tile((kt + 2) % NSTG, (kt + 2) * BK);
            cp_commit();
        }
        compute_tile(kt % NSTG);
    }

    // ---- epilogue ----
    if (!OUTH) {
        float* Db = (float*)D0 + (size_t)bz * Dbatch;
#pragma unroll
        for (int i = 0; i < 2; i++) {
            int gm = m0 + wm + i * 16;
#pragma unroll
            for (int j = 0; j < 4; j++)
                wmma::store_matrix_sync(Db + (size_t)gm * ldd + n0 + wn + j * 16,
                                        acc[i][j], ldd, wmma::mem_row_major);
        }
    } else {
        __syncthreads();                    // done reading pipeline smem
        float* stg = (float*)sm + warp * 256;
        const int sr = lane >> 1;           // 0..15 row within 16x16 frag
        const int sc = (lane & 1) * 8;      // 0 or 8: col group
#pragma unroll
        for (int i = 0; i < 2; i++) {
            int gm = m0 + wm + i * 16 + sr;
            float bb = 0.0f;
            __half* outp;
            int row;
            if (DUAL) {
                if (BIAS) bb = (gm < 64) ? bias0[gm] : bias1[gm - 64];
                outp = (__half*)(gm < 64 ? D0 : D1) + (size_t)bz * Dbatch;
                row = gm & 63;
            } else {
                if (BIAS) bb = bias0[gm];
                outp = (__half*)D0 + (size_t)bz * Dbatch;
                row = gm;
            }
#pragma unroll
            for (int j = 0; j < 4; j++) {
                wmma::store_matrix_sync(stg, acc[i][j], 16, wmma::mem_row_major);
                __syncwarp();
                const float* src = stg + sr * 16 + sc;
                __half2 h[4];
#pragma unroll
                for (int p = 0; p < 4; p++)
                    h[p] = __floats2half2_rn(src[2 * p] + bb, src[2 * p + 1] + bb);
                int gn = n0 + wn + j * 16 + sc;
                *(uint4*)(outp + (size_t)row * ldd + gn) = *(uint4*)h;
                __syncwarp();
            }
        }
    }
}

// ---------------- fused f32 -> f16 conversion (x, Wq, Wk, Wv in one launch) ----------------
#define NX4 (BATCH * CH * NPIX / 4)   // 2097152
#define NQ4 (CQK * CH / 4)            // 8192
#define NV4 (CH * CH / 4)             // 65536
__global__ __launch_bounds__(256) void f2h_all(
    const float* __restrict__ x,  const float* __restrict__ wq,
    const float* __restrict__ wk, const float* __restrict__ wv,
    __half* __restrict__ xh, __half* __restrict__ wqh,
    __half* __restrict__ wkh, __half* __restrict__ wvh)
{
    int i = blockIdx.x * 256 + threadIdx.x;
    const float* src; __half* dst; int off;
    if (i < NX4)                       { src = x;  dst = xh;  off = i; }
    else if (i < NX4 + NQ4)            { src = wq; dst = wqh; off = i - NX4; }
    else if (i < NX4 + 2 * NQ4)        { src = wk; dst = wkh; off = i - NX4 - NQ4; }
    else if (i < NX4 + 2 * NQ4 + NV4)  { src = wv; dst = wvh; off = i - NX4 - 2 * NQ4; }
    else return;
    float4 v = ((const float4*)src)[off];
    __half2* o = (__half2*)dst + 2 * (size_t)off;
    o[0] = __floats2half2_rn(v.x, v.y);
    o[1] = __floats2half2_rn(v.z, v.w);
}

// ---------------- row softmax, fp16 in/out, no max pass, 1 barrier ----------------
__global__ __launch_bounds__(256) void softmax_rows(const __half* __restrict__ E,
                                                    __half* __restrict__ A)
{
    __shared__ float row[NPIX];
    __shared__ float wsum[8];
    const __half2* e2 = (const __half2*)(E + (size_t)blockIdx.x * NPIX);
    __half2* a2 = (__half2*)(A + (size_t)blockIdx.x * NPIX);
    float2* row2 = (float2*)row;
    const int tid = threadIdx.x;
    const int lane = tid & 31, warp = tid >> 5;

    float sum = 0.0f;
#pragma unroll
    for (int i = 0; i < 8; i++) {
        int j = tid + i * 256;                 // 2048 half2 per row
        float2 f = __half22float2(e2[j]);
        float ex = __expf(f.x), ey = __expf(f.y);
        row2[j] = make_float2(ex, ey);
        sum += ex + ey;
    }
#pragma unroll
    for (int o = 16; o > 0; o >>= 1)
        sum += __shfl_xor_sync(0xFFFFFFFFu, sum, o);
    if (lane == 0) wsum[warp] = sum;
    __syncthreads();
    float tot = 0.0f;
#pragma unroll
    for (int w = 0; w < 8; w++) tot += wsum[w];
    const float inv = 1.0f / tot;

#pragma unroll
    for (int i = 0; i < 8; i++) {
        int j = tid + i * 256;
        float2 v = row2[j];
        a2[j] = __floats2half2_rn(v.x * inv, v.y * inv);
    }
}

// ---------------- residual write + per-channel batch stats (ao fp16) ----------------
__global__ __launch_bounds__(256) void residual_stats(
    const __half* __restrict__ ao, const float* __restrict__ x,
    const float* __restrict__ gamma, float* __restrict__ out,
    float* __restrict__ mean, float* __restrict__ var)
{
    __shared__ float w1[8], w2[8];
    const int c = blockIdx.x;
    const float g = gamma[0];
    const int lane = threadIdx.x & 31, warp = threadIdx.x >> 5;
    float s1 = 0.0f, s2 = 0.0f;
#pragma unroll
    for (int b = 0; b < BATCH; b++) {
        const size_t rowoff = ((size_t)b * CH + c) * NPIX;
        const uint4* a8 = (const uint4*)(ao + rowoff);   // 8 halves per load
        const float4* x4 = (const float4*)(x + rowoff);
        float4* o4 = (float4*)(out + rowoff);
        for (int n = threadIdx.x; n < NPIX / 8; n += 256) {
            uint4 av = a8[n];
            const __half2* h2 = (const __half2*)&av;
            float4 xa = x4[2 * n], xb = x4[2 * n + 1];
            float2 f0 = __half22float2(h2[0]), f1 = __half22float2(h2[1]);
            float2 f2 = __half22float2(h2[2]), f3 = __half22float2(h2[3]);
            float4 ra, rb;
            ra.x = g * f0.x + xa.x; ra.y = g * f0.y + xa.y;
            ra.z = g * f1.x + xa.z; ra.w = g * f1.y + xa.w;
            rb.x = g * f2.x + xb.x; rb.y = g * f2.y + xb.y;
            rb.z = g * f3.x + xb.z; rb.w = g * f3.y + xb.w;
            o4[2 * n] = ra;
            o4[2 * n + 1] = rb;
            s1 += ra.x + ra.y + ra.z + ra.w + rb.x + rb.y + rb.z + rb.w;
            s2 += ra.x * ra.x + ra.y * ra.y + ra.z * ra.z + ra.w * ra.w
                + rb.x * rb.x + rb.y * rb.y + rb.z * rb.z + rb.w * rb.w;
        }
    }
#pragma unroll
    for (int o = 16; o > 0; o >>= 1) {
        s1 += __shfl_xor_sync(0xFFFFFFFFu, s1, o);
        s2 += __shfl_xor_sync(0xFFFFFFFFu, s2, o);
    }
    if (lane == 0) { w1[warp] = s1; w2[warp] = s2; }
    __syncthreads();
    if (threadIdx.x == 0) {
        float t1 = 0.0f, t2 = 0.0f;
#pragma unroll
        for (int w = 0; w < 8; w++) { t1 += w1[w]; t2 += w2[w]; }
        const float cnt = (float)(BATCH * NPIX);
        float m = t1 / cnt;
        mean[c] = m;
        var[c] = t2 / cnt - m * m;
    }
}

// ---------------- BN apply, in place on d_out ----------------
__global__ __launch_bounds__(256) void bn_apply(
    float* __restrict__ out, const float* __restrict__ mean,
    const float* __restrict__ var, const float* __restrict__ w,
    const float* __restrict__ bb)
{
    size_t i4 = (size_t)blockIdx.x * 256 + threadIdx.x;
    int c = (int)((i4 >> 10) & (CH - 1));
    float sc = rsqrtf(var[c] + EPS) * w[c];
    float sh = bb[c] - mean[c] * sc;
    float4 r = ((float4*)out)[i4];
    r.x = r.x * sc + sh;
    r.y = r.y * sc + sh;
    r.z = r.z * sc + sh;
    r.w = r.w * sc + sh;
    ((float4*)out)[i4] = r;
}

// ---------------- launch ----------------
extern "C" void kernel_launch(void* const* d_in, const int* in_sizes, int n_in,
                              void* d_out, int out_size)
{
    const float* x     = (const float*)d_in[0];
    const float* Wq    = (const float*)d_in[1];
    const float* bq    = (const float*)d_in[2];
    const float* Wk    = (const float*)d_in[3];
    const float* bk    = (const float*)d_in[4];
    const float* Wv    = (const float*)d_in[5];
    const float* bv    = (const float*)d_in[6];
    const float* gamma = (const float*)d_in[7];
    const float* bn_w  = (const float*)d_in[8];
    const float* bn_b  = (const float*)d_in[9];
    float* out = (float*)d_out;

    __half *xh, *wqh, *wkh, *wvh, *qh, *kh, *vh, *eh, *attnh, *aoh;
    float *mean, *var;
    cudaGetSymbolAddress((void**)&xh,      g_xh);
    cudaGetSymbolAddress((void**)&wqh,     g_wqh);
    cudaGetSymbolAddress((void**)&wkh,     g_wkh);
    cudaGetSymbolAddress((void**)&wvh,     g_wvh);
    cudaGetSymbolAddress((void**)&qh,      g_qh);
    cudaGetSymbolAddress((void**)&kh,      g_kh);
    cudaGetSymbolAddress((void**)&vh,      g_vh);
    cudaGetSymbolAddress((void**)&eh,      g_eh);
    cudaGetSymbolAddress((void**)&attnh,   g_attnh);
    cudaGetSymbolAddress((void**)&aoh,     g_aoh);
    cudaGetSymbolAddress((void**)&mean,    g_mean);
    cudaGetSymbolAddress((void**)&var,     g_var);

    // dynamic smem sizes (3 stages)
    const int smem00 = NSTG * (BM * LDA0 + BK * LDB0) * (int)sizeof(__half); // 56832
    const int smem10 = NSTG * (BK * LDA1 + BK * LDB0) * (int)sizeof(__half); // 52224
    const int smem01 = NSTG * (BM * LDA0 + BN * LDB1) * (int)sizeof(__half); // 61440
    cudaFuncSetAttribute(hgemm<0, 0, true,  true,  true>,
                         cudaFuncAttributeMaxDynamicSharedMemorySize, smem00);
    cudaFuncSetAttribute(hgemm<0, 0, false, true,  true>,
                         cudaFuncAttributeMaxDynamicSharedMemorySize, smem00);
    cudaFuncSetAttribute(hgemm<1, 0, false, false, true>,
                         cudaFuncAttributeMaxDynamicSharedMemorySize, smem10);
    cudaFuncSetAttribute(hgemm<0, 1, false, false, true>,
                         cudaFuncAttributeMaxDynamicSharedMemorySize, smem01);

    const size_t xbs = (size_t)CH * NPIX;     // x / xh / vh / aoh batch stride
    const size_t qbs = (size_t)CQK * NPIX;    // qh / kh batch stride
    const size_t ebs = (size_t)NPIX * NPIX;   // energy / attn batch stride

    // 1) convert inputs to half (single launch)
    f2h_all<<<(NX4 + 2 * NQ4 + NV4 + 255) / 256, 256>>>(
        x, Wq, Wk, Wv, xh, wqh, wkh, wvh);

    // 2) q,k = (Wq||Wk) @ x  -> half. M=128 (dual 64+64), K=512
    hgemm<0, 0, true, true, true><<<dim3(NPIX / BN, 1, BATCH), NTHR, smem00>>>(
        wqh, wkh, 0, CH, xh, xbs, NPIX, qh, kh, qbs, NPIX, bq, bk, CH);

    // 3) v = Wv @ x -> half. M=512, K=512
    hgemm<0, 0, false, true, true><<<dim3(NPIX / BN, CH / BM, BATCH), NTHR, smem00>>>(
        wvh, nullptr, 0, CH, xh, xbs, NPIX, vh, nullptr, xbs, NPIX, bv, nullptr, CH);

    // 4) energy(i,j) = sum_k q(k,i)*k(k,j) -> fp16. M=N=4096, K=64
    hgemm<1, 0, false, false, true><<<dim3(NPIX / BN, NPIX / BM, BATCH), NTHR, smem10>>>(
        qh, nullptr, qbs, NPIX, kh, qbs, NPIX, eh, nullptr, ebs, NPIX,
        nullptr, nullptr, CQK);

    // 5) softmax rows (fp16 in, no max pass) -> half attn
    softmax_rows<<<BATCH * NPIX, 256>>>(eh, attnh);

    // 6) ao(c,i) = sum_j v(c,j)*attn(i,j) -> fp16. M=512, K=4096
    hgemm<0, 1, false, false, true><<<dim3(NPIX / BN, CH / BM, BATCH), NTHR, smem01>>>(
        vh, nullptr, xbs, NPIX, attnh, ebs, NPIX, aoh, nullptr, xbs, NPIX,
        nullptr, nullptr, NPIX);

    // 7) residual write + stats (fp16 ao), then BN in place on d_out
    residual_stats<<<CH, 256>>>(aoh, x, gamma, out, mean, var);
    bn_apply<<<(unsigned)(((size_t)BATCH * CH * NPIX / 4) / 256), 256>>>(
        out, mean, var, bn_w, bn_b);
}